// round 15
// baseline (speedup 1.0000x reference)
#include <cuda_runtime.h>
#include <cuda_fp16.h>
#include <math.h>
#include <stdint.h>

#define BB 32
#define TT 1024
#define DD 768
#define HH 1024
#define BT (BB*TT)

// ---------------- scratch (device globals; no allocations) ----------------
__device__ __half d_xh[(size_t)BT * DD];     // fp16 hi of 32*LN(x)
__device__ __half d_xl[(size_t)BT * DD];     // fp16 lo residual
__device__ __half d_w1ht[(size_t)HH * DD];   // fp16 hi of 32*w1, transposed [n][k]
__device__ __half d_w1lt[(size_t)HH * DD];   // fp16 lo, transposed [n][k]
__device__ float d_part[8][BT];              // per-N-tile score partials
__device__ int   d_validx[BT];
__device__ int   d_rowof[BT];
__device__ int   d_nv;
__device__ float d_Teff[BB];
__device__ float d_snorm[BT];
__device__ float d_rankv[BT];
__device__ int   d_pos[BT];
__device__ float d_gall[3][BT];
__device__ float d_keff[3][BB];
__device__ float d_poolacc[4][BB][DD];

#define OFF_HARD  32768
#define OFF_RECON 131072
#define OFF_LOSS  131073
#define OFF_RHOE  131076

// ---------------- helpers ----------------
__device__ __forceinline__ float bsum1024(float v, float* red) {
    int t = threadIdx.x;
    red[t] = v; __syncthreads();
    #pragma unroll
    for (int o = 512; o > 0; o >>= 1) {
        if (t < o) red[t] += red[t + o];
        __syncthreads();
    }
    float r = red[0]; __syncthreads();
    return r;
}

__device__ __forceinline__ void mma_f16(float* c, const unsigned* a,
                                        unsigned b0, unsigned b1) {
    asm volatile(
        "mma.sync.aligned.m16n8k16.row.col.f32.f16.f16.f32 "
        "{%0,%1,%2,%3}, {%4,%5,%6,%7}, {%8,%9}, {%0,%1,%2,%3};"
        : "+f"(c[0]), "+f"(c[1]), "+f"(c[2]), "+f"(c[3])
        : "r"(a[0]), "r"(a[1]), "r"(a[2]), "r"(a[3]), "r"(b0), "r"(b1));
}

__device__ __forceinline__ void ldsm4(unsigned* r, uint32_t addr) {
    asm volatile("ldmatrix.sync.aligned.m8n8.x4.shared.b16 {%0,%1,%2,%3}, [%4];"
                 : "=r"(r[0]), "=r"(r[1]), "=r"(r[2]), "=r"(r[3]) : "r"(addr));
}

__device__ __forceinline__ uint32_t s2u32(const void* p) {
    uint32_t a;
    asm("{ .reg .u64 t; cvta.to.shared.u64 t, %1; cvt.u32.u64 %0, t; }" : "=r"(a) : "l"(p));
    return a;
}
__device__ __forceinline__ void cp16(uint32_t saddr, const void* g) {
    asm volatile("cp.async.cg.shared.global [%0], [%1], 16;"
                 :: "r"(saddr), "l"(g) : "memory");
}
#define CP_COMMIT() asm volatile("cp.async.commit_group;" ::: "memory")
#define CP_WAIT(n)  asm volatile("cp.async.wait_group %0;" :: "n"(n) : "memory")

// ---------------- 1) compact valid tokens + zero accumulators ----------------
__global__ void k_compact(const int* __restrict__ attn) {
    int t = threadIdx.x, lane = t & 31, w = t >> 5;
    __shared__ int wTot[32], wOff[32];
    __shared__ int sBase, sCnt;
    if (t == 0) sBase = 0;
    __syncthreads();
    for (int b = 0; b < BB; b++) {
        int idx = b * TT + t;
        int flag = (attn[idx] != 0);
        unsigned m = __ballot_sync(0xffffffffu, flag);
        int pin = __popc(m & ((1u << lane) - 1u));
        if (lane == 0) wTot[w] = __popc(m);
        __syncthreads();
        if (t < 32) {
            int v = wTot[t], x = v;
            #pragma unroll
            for (int o = 1; o < 32; o <<= 1) {
                int y = __shfl_up_sync(0xffffffffu, x, o);
                if (lane >= o) x += y;
            }
            wOff[t] = x - v;
            if (t == 31) sCnt = x;
        }
        __syncthreads();
        int p = sBase + wOff[w] + pin;
        if (flag) { d_validx[p] = idx; d_rowof[idx] = p; }
        else      { d_rowof[idx] = -1; }
        __syncthreads();
        if (t == 0) { d_Teff[b] = (float)sCnt; sBase += sCnt; }
        __syncthreads();
    }
    if (t == 0) d_nv = sBase;
    float* pa = (float*)d_poolacc;
    for (int i = t; i < 4 * BB * DD; i += 1024) pa[i] = 0.f;
}

// ---------------- 1b) split + transpose 32*w1 -> [n][k] fp16 hi/lo -----------
__global__ __launch_bounds__(256) void k_splitw_t(const float* __restrict__ w1) {
    __shared__ float th[32][33], tl[32][33];
    int nx = blockIdx.x * 32;   // H dim
    int ky = blockIdx.y * 32;   // D dim
    int tx = threadIdx.x & 31, ty = threadIdx.x >> 5;   // 32x8
    #pragma unroll
    for (int j = 0; j < 4; j++) {
        int k = ky + ty + j * 8;
        float v = w1[(size_t)k * HH + nx + tx] * 32.0f;
        float h = __half2float(__float2half_rn(v));
        th[ty + j * 8][tx] = h;
        tl[ty + j * 8][tx] = v - h;
    }
    __syncthreads();
    #pragma unroll
    for (int j = 0; j < 4; j++) {
        int n = nx + ty + j * 8;
        d_w1ht[(size_t)n * DD + ky + tx] = __float2half_rn(th[tx][ty + j * 8]);
        d_w1lt[(size_t)n * DD + ky + tx] = __float2half_rn(tl[tx][ty + j * 8]);
    }
}

// ---------------- 2) LayerNorm (compacted) + fp16 hi/lo split (x32) ----------
__global__ __launch_bounds__(192) void k_ln(const float* __restrict__ emb,
                                            const float* __restrict__ g,
                                            const float* __restrict__ bb) {
    int r = blockIdx.x;
    if (r >= d_nv) return;
    int tok = d_validx[r];
    const float4* x4 = (const float4*)(emb + (size_t)tok * DD);
    int t = threadIdx.x;
    float4 v = x4[t];
    __shared__ float red[192];

    red[t] = v.x + v.y + v.z + v.w; __syncthreads();
    if (t < 64) red[t] += red[t + 64] + red[t + 128];
    __syncthreads();
    #pragma unroll
    for (int o = 32; o > 0; o >>= 1) { if (t < o) red[t] += red[t + o]; __syncthreads(); }
    float mu = red[0] * (1.0f / (float)DD);
    __syncthreads();

    float ex = v.x - mu, ey = v.y - mu, ez = v.z - mu, ew = v.w - mu;
    red[t] = ex * ex + ey * ey + ez * ez + ew * ew; __syncthreads();
    if (t < 64) red[t] += red[t + 64] + red[t + 128];
    __syncthreads();
    #pragma unroll
    for (int o = 32; o > 0; o >>= 1) { if (t < o) red[t] += red[t + o]; __syncthreads(); }
    float inv = rsqrtf(red[0] * (1.0f / (float)DD) + 1e-5f);

    float4 gv = ((const float4*)g)[t];
    float4 bv = ((const float4*)bb)[t];
    float o0 = (ex * inv * gv.x + bv.x) * 32.0f;
    float o1 = (ey * inv * gv.y + bv.y) * 32.0f;
    float o2 = (ez * inv * gv.z + bv.z) * 32.0f;
    float o3 = (ew * inv * gv.w + bv.w) * 32.0f;
    __half h0 = __float2half_rn(o0), h1 = __float2half_rn(o1);
    __half h2 = __float2half_rn(o2), h3 = __float2half_rn(o3);
    __half l0 = __float2half_rn(o0 - __half2float(h0));
    __half l1 = __float2half_rn(o1 - __half2float(h1));
    __half l2 = __float2half_rn(o2 - __half2float(h2));
    __half l3 = __float2half_rn(o3 - __half2float(h3));
    __half2* ph = (__half2*)(d_xh + (size_t)r * DD);
    __half2* pl = (__half2*)(d_xl + (size_t)r * DD);
    ph[2 * t]     = __halves2half2(h0, h1);
    ph[2 * t + 1] = __halves2half2(h2, h3);
    pl[2 * t]     = __halves2half2(l0, l1);
    pl[2 * t + 1] = __halves2half2(l2, l3);
}

// ---------------- 3) GEMM: fp16 2-split m16n8k16 + ldmatrix + cp.async -------
// CTA 128x128, 256 thr (8 warps: 4m x 2n; warp 32x64).
// Pipeline stages now carry k=32 (64B payload in the same 80B rows):
// half the stages -> half the barriers. Identical smem footprint & mma order.
#define MATB 20480          // 2 stages x 128 rows x 80B
#define STGB 10240
#define RB_B  81920         // rbuf 128x2 floats
#define B1_B  82944         // 128 floats
#define W2_B  83456         // 128 floats
#define GEMM_SMEM_BYTES 83968
#define NST (DD / 32)       // 24 k32-stages

__global__ __launch_bounds__(256, 2) void k_gemm(const float* __restrict__ b1,
                                                 const float* __restrict__ w2) {
    extern __shared__ char smc[];
    int nv = d_nv;
    int n0 = blockIdx.x * 128;
    int row0 = blockIdx.y * 128;
    if (row0 >= nv) return;

    int tid = threadIdx.x;
    int lane = tid & 31, wid = tid >> 5;
    int warp_m = wid >> 1, warp_n = wid & 1;
    int lq = lane >> 2, lp = lane & 3;

    float* b1s = (float*)(smc + B1_B);
    float* w2s = (float*)(smc + W2_B);
    if (tid < 128) { b1s[tid] = b1[n0 + tid]; w2s[tid] = w2[n0 + tid]; }

    // loader: mat = tid>>6 (0=Ah 1=Al 2=Bh 3=Bl), 64 thr/mat, 2 rows x 4 chunks
    int mat = tid >> 6;
    int t2 = tid & 63;
    uint32_t smem_base = s2u32(smc);
    const __half* gsrc;
    int gb;
    if      (mat == 0) { gsrc = d_xh;   gb = row0; }
    else if (mat == 1) { gsrc = d_xl;   gb = row0; }
    else if (mat == 2) { gsrc = d_w1ht; gb = n0; }
    else               { gsrc = d_w1lt; gb = n0; }
    int r0 = t2 * 2;
    uint32_t sMat = smem_base + mat * MATB;

    float acc[2][8][4];
    #pragma unroll
    for (int mt = 0; mt < 2; mt++)
        #pragma unroll
        for (int nt = 0; nt < 8; nt++)
            #pragma unroll
            for (int q = 0; q < 4; q++) acc[mt][nt][q] = 0.f;

    #define PREFETCH(ii, ss) do {                                              \
        const __half* _g0 = gsrc + (size_t)(gb + r0) * DD + (ii) * 32;         \
        const __half* _g1 = _g0 + DD;                                          \
        uint32_t _s = sMat + (ss) * STGB + r0 * 80;                            \
        cp16(_s,       _g0);      cp16(_s + 16, _g0 + 8);                      \
        cp16(_s + 32,  _g0 + 16); cp16(_s + 48, _g0 + 24);                     \
        cp16(_s + 80,  _g1);      cp16(_s + 96, _g1 + 8);                      \
        cp16(_s + 112, _g1 + 16); cp16(_s + 128, _g1 + 24);                    \
    } while (0)

    PREFETCH(0, 0);
    CP_COMMIT();

    uint32_t aH = smem_base;
    uint32_t aL = smem_base + MATB;
    uint32_t bH = smem_base + 2 * MATB;
    uint32_t bL = smem_base + 3 * MATB;

    // ldmatrix lane offsets (computed once):
    uint32_t aOff = (uint32_t)(((warp_m * 32) + (lane & 15)) * 80 + (lane >> 4) * 16);
    uint32_t bOff = (uint32_t)(((warp_n * 64) + ((lane >> 4) << 3) + (lane & 7)) * 80
                               + ((lane >> 3) & 1) * 16);

    for (int i = 0; i < NST; i++) {
        int s = i & 1;
        if (i + 1 < NST) {
            PREFETCH(i + 1, s ^ 1);
            CP_COMMIT();
            CP_WAIT(1);
        } else {
            CP_WAIT(0);
        }
        __syncthreads();

        uint32_t stg = s * STGB;
        #pragma unroll
        for (int ks = 0; ks < 2; ks++) {       // two k16 sub-steps, ascending k
            uint32_t ko = ks * 32;             // byte offset within 80B row
            unsigned ah[2][4], al[2][4];
            #pragma unroll
            for (int mt = 0; mt < 2; mt++) {
                ldsm4(ah[mt], aH + stg + aOff + ko + mt * 1280);
                ldsm4(al[mt], aL + stg + aOff + ko + mt * 1280);
            }
            #pragma unroll
            for (int p = 0; p < 4; p++) {      // nt-pairs (2p, 2p+1)
                unsigned bhf[4], blf[4];
                ldsm4(bhf, bH + stg + bOff + ko + p * 1280);
                ldsm4(blf, bL + stg + bOff + ko + p * 1280);
                #pragma unroll
                for (int h = 0; h < 2; h++) {
                    int nt = 2 * p + h;
                    unsigned b0h = bhf[h * 2], b1h = bhf[h * 2 + 1];
                    unsigned b0l = blf[h * 2], b1l = blf[h * 2 + 1];
                    #pragma unroll
                    for (int mt = 0; mt < 2; mt++) {
                        mma_f16(acc[mt][nt], ah[mt], b0h, b1h);  // hi*hi
                        mma_f16(acc[mt][nt], ah[mt], b0l, b1l);  // hi*lo
                        mma_f16(acc[mt][nt], al[mt], b0h, b1h);  // lo*hi
                    }
                }
            }
        }
        __syncthreads();
    }

    // epilogue: unscale (1/1024) + bias + exact GELU + w2, warp-reduce 64 cols
    float* rbuf = (float*)(smc + RB_B);
    #pragma unroll
    for (int mt = 0; mt < 2; mt++) {
        #pragma unroll
        for (int half = 0; half < 2; half++) {
            float p = 0.f;
            #pragma unroll
            for (int nt = 0; nt < 8; nt++) {
                int col = warp_n * 64 + nt * 8 + 2 * lp;
                float v0 = acc[mt][nt][half * 2]     * (1.0f / 1024.0f);
                float v1 = acc[mt][nt][half * 2 + 1] * (1.0f / 1024.0f);
                float h0 = v0 + b1s[col];
                float h1 = v1 + b1s[col + 1];
                float g0 = 0.5f * h0 * (1.0f + erff(h0 * 0.70710678118654752440f));
                float g1 = 0.5f * h1 * (1.0f + erff(h1 * 0.70710678118654752440f));
                p += g0 * w2s[col] + g1 * w2s[col + 1];
            }
            p += __shfl_xor_sync(0xffffffffu, p, 1);
            p += __shfl_xor_sync(0xffffffffu, p, 2);
            if (lp == 0)
                rbuf[(warp_m * 32 + mt * 16 + half * 8 + lq) * 2 + warp_n] = p;
        }
    }
    __syncthreads();
    if (tid < 128) {
        int row = row0 + tid;
        if (row < nv)
            d_part[blockIdx.x][row] = rbuf[tid * 2] + rbuf[tid * 2 + 1];
    }
}

// ---------------- 4a) per-batch score normalization ----------------
__global__ __launch_bounds__(1024) void k_score(const int* __restrict__ attn,
                                                const float* __restrict__ b2) {
    int b = blockIdx.x, j = threadIdx.x;
    __shared__ float red[1024];
    int idx = b * TT + j;
    float a = (attn[idx] != 0) ? 1.f : 0.f;
    float sraw = 0.f;
    if (a > 0.f) {
        int row = d_rowof[idx];
        float s = 0.f;
        #pragma unroll
        for (int n = 0; n < 8; n++) s += d_part[n][row];
        sraw = s + b2[0];
    }
    float denom = fmaxf(d_Teff[b], 1.0f);
    float S1 = bsum1024(sraw, red);
    float mean = S1 / denom;
    float dv = sraw - mean;
    float S2 = bsum1024(dv * dv * a, red);
    float var = S2 / denom;
    d_snorm[idx] = (sraw - mean) / sqrtf(var + 1e-6f);
}

// ---------------- 4b) pairwise soft-rank (chip-wide, MUFU path) --------------
__global__ __launch_bounds__(256) void k_pair(const int* __restrict__ attn) {
    int b = blockIdx.x;
    __shared__ float sn[1024];
    for (int i = threadIdx.x; i < 1024; i += 256) sn[i] = d_snorm[b * TT + i];
    __syncthreads();
    int j = blockIdx.y * 256 + threadIdx.x;
    int idx = b * TT + j;
    if (attn[idx] == 0) { d_rankv[idx] = 1e9f; return; }
    float sj = sn[j];
    float a0 = 0.f, a1 = 0.f, a2 = 0.f, a3 = 0.f;
    #pragma unroll 2
    for (int i = 0; i < 1024; i += 4) {
        float e0 = __expf((sn[i]     - sj) * 20.0f); float s0 = __fdividef(1.f, 1.f + e0); a0 += s0 * s0;
        float e1 = __expf((sn[i + 1] - sj) * 20.0f); float s1 = __fdividef(1.f, 1.f + e1); a1 += s1 * s1;
        float e2 = __expf((sn[i + 2] - sj) * 20.0f); float s2 = __fdividef(1.f, 1.f + e2); a2 += s2 * s2;
        float e3 = __expf((sn[i + 3] - sj) * 20.0f); float s3 = __fdividef(1.f, 1.f + e3); a3 += s3 * s3;
    }
    d_rankv[idx] = 1.f + ((a0 + a1) + (a2 + a3));
}

// ---------------- 4c) ascending-rank position (chip-wide) ----------------
__global__ __launch_bounds__(256) void k_pos() {
    int b = blockIdx.x;
    __shared__ float rk[1024];
    for (int i = threadIdx.x; i < 1024; i += 256) rk[i] = d_rankv[b * TT + i];
    __syncthreads();
    int j = blockIdx.y * 256 + threadIdx.x;
    float r = rk[j];
    int pos = 0;
    #pragma unroll 4
    for (int i = 0; i < 1024; i++) {
        float ri = rk[i];
        pos += (ri < r) || (ri == r && i < j);
    }
    d_pos[b * TT + j] = pos;
}

// ---------------- 4d) gates + hard masks + per-batch sums ----------------
__global__ __launch_bounds__(1024) void k_gate(const int* __restrict__ attn,
                                               float* __restrict__ out) {
    int b = blockIdx.x, j = threadIdx.x;
    __shared__ float red[1024];
    int idx = b * TT + j;
    float a = (attn[idx] != 0) ? 1.f : 0.f;
    float r = d_rankv[idx];
    float fpos = (float)d_pos[idx];
    float Teff = d_Teff[b];

    const float rhos[3] = {0.1f, 0.25f, 0.5f};
    #pragma unroll
    for (int q = 0; q < 3; q++) {
        float k = fmaxf(rintf(rhos[q] * Teff), 1.0f);
        float gate = (a > 0.f) ? 1.f / (1.f + __expf(-(k - r) * 5.0f)) : 0.f;
        float Sg = bsum1024(gate, red);
        float g = gate / fmaxf(Sg, 1e-8f) * k;
        d_gall[q][idx] = g;
        if (q == 2) out[idx] = g;
        out[OFF_HARD + q * BT + idx] = (fpos < k) ? 1.f : 0.f;
        float Sg2 = bsum1024(g, red);
        if (j == 0) {
            d_keff[q][b] = Sg2;
            out[OFF_RHOE + q * BB + b] = Sg2 / fmaxf(Teff, 1.0f);
        }
    }
}

// ---------------- 5) pooled representations (4 weightings, one pass) ---------
__global__ __launch_bounds__(256) void k_pool(const int* __restrict__ ids,
                                              const int* __restrict__ attn,
                                              const float* __restrict__ etab) {
    int b = blockIdx.x;
    int t0 = blockIdx.y * 128;
    int tid = threadIdx.x;
    float accF[3] = {0, 0, 0}, ac0[3] = {0, 0, 0}, ac1[3] = {0, 0, 0}, ac2[3] = {0, 0, 0};
    for (int t = t0; t < t0 + 128; t++) {
        int idx = b * TT + t;
        if (attn[idx] == 0) continue;
        int id = ids[idx];
        float w0 = d_gall[0][idx], w1v = d_gall[1][idx], w2v = d_gall[2][idx];
        const float* row = etab + (size_t)id * DD;
        #pragma unroll
        for (int i = 0; i < 3; i++) {
            float v = __ldg(row + tid + 256 * i);
            accF[i] += v; ac0[i] += v * w0; ac1[i] += v * w1v; ac2[i] += v * w2v;
        }
    }
    #pragma unroll
    for (int i = 0; i < 3; i++) {
        int d = tid + 256 * i;
        atomicAdd(&d_poolacc[0][b][d], accF[i]);
        atomicAdd(&d_poolacc[1][b][d], ac0[i]);
        atomicAdd(&d_poolacc[2][b][d], ac1[i]);
        atomicAdd(&d_poolacc[3][b][d], ac2[i]);
    }
}

// ---------------- 6) losses ----------------
__global__ __launch_bounds__(1024) void k_final(float* __restrict__ out) {
    int t = threadIdx.x;
    __shared__ float red[1024];
    __shared__ float sl[3];
    for (int q = 0; q < 3; q++) {
        float s = 0.f;
        for (int n = t; n < BB * DD; n += 1024) {
            int b = n / DD, d = n % DD;
            float Te = d_Teff[b];
            float full = d_poolacc[0][b][d] / fmaxf(Te, 1e-9f);
            float pred = d_poolacc[1 + q][b][d] / fmaxf(d_keff[q][b], 1e-9f);
            float df = pred - full;
            s += df * df;
        }
        float S = bsum1024(s, red);
        if (t == 0) sl[q] = S / (float)(BB * DD);
        __syncthreads();
    }
    if (t == 0) {
        float l0 = sl[0], l1 = sl[1], l2 = sl[2];
        out[OFF_RECON] = ((l0 + l1) + l2) / 3.0f;
        out[OFF_LOSS + 0] = l0;
        out[OFF_LOSS + 1] = l1;
        out[OFF_LOSS + 2] = l2;
    }
}

// ---------------- launch ----------------
extern "C" void kernel_launch(void* const* d_in, const int* in_sizes, int n_in,
                              void* d_out, int out_size) {
    const int*   ids  = (const int*)d_in[0];
    const float* emb  = (const float*)d_in[1];
    const int*   attn = (const int*)d_in[2];
    const float* ln_g = (const float*)d_in[3];
    const float* ln_b = (const float*)d_in[4];
    const float* w1   = (const float*)d_in[5];
    const float* b1   = (const float*)d_in[6];
    const float* w2   = (const float*)d_in[7];
    const float* b2   = (const float*)d_in[8];
    const float* etab = (const float*)d_in[9];
    float* out = (float*)d_out;

    static int smem_set = 0;
    if (!smem_set) {
        cudaFuncSetAttribute(k_gemm, cudaFuncAttributeMaxDynamicSharedMemorySize,
                             GEMM_SMEM_BYTES);
        smem_set = 1;
    }

    k_compact<<<1, 1024>>>(attn);
    dim3 gw(HH / 32, DD / 32);
    k_splitw_t<<<gw, 256>>>(w1);
    k_ln<<<BT, 192>>>(emb, ln_g, ln_b);
    dim3 gg(HH / 128, BT / 128);           // x = col tile fastest -> A reuse in L2
    k_gemm<<<gg, 256, GEMM_SMEM_BYTES>>>(b1, w2);
    k_score<<<BB, 1024>>>(attn, b2);
    dim3 gr(BB, TT / 256);
    k_pair<<<gr, 256>>>(attn);
    k_pos<<<gr, 256>>>();
    k_gate<<<BB, 1024>>>(attn, out);
    dim3 gp(BB, TT / 128);
    k_pool<<<gp, 256>>>(ids, attn, etab);
    k_final<<<1, 1024>>>(out);
}

// round 16
// speedup vs baseline: 1.0987x; 1.0987x over previous
#include <cuda_runtime.h>
#include <cuda_fp16.h>
#include <math.h>
#include <stdint.h>

#define BB 32
#define TT 1024
#define DD 768
#define HH 1024
#define BT (BB*TT)

// ---------------- scratch (device globals; no allocations) ----------------
__device__ __half d_xh[(size_t)BT * DD];     // fp16 hi of 32*LN(x)
__device__ __half d_xl[(size_t)BT * DD];     // fp16 lo residual
__device__ __half d_w1ht[(size_t)HH * DD];   // fp16 hi of 32*w1, transposed [n][k]
__device__ __half d_w1lt[(size_t)HH * DD];   // fp16 lo, transposed [n][k]
__device__ float d_part[8][BT];              // per-N-tile score partials
__device__ int   d_validx[BT];
__device__ int   d_rowof[BT];
__device__ int   d_nv;
__device__ float d_Teff[BB];
__device__ float d_snorm[BT];
__device__ float d_rankv[BT];
__device__ int   d_pos[BT];
__device__ float d_gall[3][BT];
__device__ float d_keff[3][BB];
__device__ float d_poolacc[4][BB][DD];

#define OFF_HARD  32768
#define OFF_RECON 131072
#define OFF_LOSS  131073
#define OFF_RHOE  131076

// ---------------- helpers ----------------
__device__ __forceinline__ float bsum1024(float v, float* red) {
    int t = threadIdx.x;
    red[t] = v; __syncthreads();
    #pragma unroll
    for (int o = 512; o > 0; o >>= 1) {
        if (t < o) red[t] += red[t + o];
        __syncthreads();
    }
    float r = red[0]; __syncthreads();
    return r;
}

__device__ __forceinline__ void mma_f16(float* c, const unsigned* a,
                                        unsigned b0, unsigned b1) {
    asm volatile(
        "mma.sync.aligned.m16n8k16.row.col.f32.f16.f16.f32 "
        "{%0,%1,%2,%3}, {%4,%5,%6,%7}, {%8,%9}, {%0,%1,%2,%3};"
        : "+f"(c[0]), "+f"(c[1]), "+f"(c[2]), "+f"(c[3])
        : "r"(a[0]), "r"(a[1]), "r"(a[2]), "r"(a[3]), "r"(b0), "r"(b1));
}

__device__ __forceinline__ void ldsm4(unsigned* r, uint32_t addr) {
    asm volatile("ldmatrix.sync.aligned.m8n8.x4.shared.b16 {%0,%1,%2,%3}, [%4];"
                 : "=r"(r[0]), "=r"(r[1]), "=r"(r[2]), "=r"(r[3]) : "r"(addr));
}

__device__ __forceinline__ uint32_t s2u32(const void* p) {
    uint32_t a;
    asm("{ .reg .u64 t; cvta.to.shared.u64 t, %1; cvt.u32.u64 %0, t; }" : "=r"(a) : "l"(p));
    return a;
}
__device__ __forceinline__ void cp16(uint32_t saddr, const void* g) {
    asm volatile("cp.async.cg.shared.global [%0], [%1], 16;"
                 :: "r"(saddr), "l"(g) : "memory");
}
#define CP_COMMIT() asm volatile("cp.async.commit_group;" ::: "memory")
#define CP_WAIT(n)  asm volatile("cp.async.wait_group %0;" :: "n"(n) : "memory")

// ---------------- 1) compact valid tokens + zero accumulators ----------------
__global__ void k_compact(const int* __restrict__ attn) {
    int t = threadIdx.x, lane = t & 31, w = t >> 5;
    __shared__ int wTot[32], wOff[32];
    __shared__ int sBase, sCnt;
    if (t == 0) sBase = 0;
    __syncthreads();
    for (int b = 0; b < BB; b++) {
        int idx = b * TT + t;
        int flag = (attn[idx] != 0);
        unsigned m = __ballot_sync(0xffffffffu, flag);
        int pin = __popc(m & ((1u << lane) - 1u));
        if (lane == 0) wTot[w] = __popc(m);
        __syncthreads();
        if (t < 32) {
            int v = wTot[t], x = v;
            #pragma unroll
            for (int o = 1; o < 32; o <<= 1) {
                int y = __shfl_up_sync(0xffffffffu, x, o);
                if (lane >= o) x += y;
            }
            wOff[t] = x - v;
            if (t == 31) sCnt = x;
        }
        __syncthreads();
        int p = sBase + wOff[w] + pin;
        if (flag) { d_validx[p] = idx; d_rowof[idx] = p; }
        else      { d_rowof[idx] = -1; }
        __syncthreads();
        if (t == 0) { d_Teff[b] = (float)sCnt; sBase += sCnt; }
        __syncthreads();
    }
    if (t == 0) d_nv = sBase;
    float* pa = (float*)d_poolacc;
    for (int i = t; i < 4 * BB * DD; i += 1024) pa[i] = 0.f;
}

// ---------------- 1b) split + transpose 32*w1 -> [n][k] fp16 hi/lo -----------
__global__ __launch_bounds__(256) void k_splitw_t(const float* __restrict__ w1) {
    __shared__ float th[32][33], tl[32][33];
    int nx = blockIdx.x * 32;   // H dim
    int ky = blockIdx.y * 32;   // D dim
    int tx = threadIdx.x & 31, ty = threadIdx.x >> 5;   // 32x8
    #pragma unroll
    for (int j = 0; j < 4; j++) {
        int k = ky + ty + j * 8;
        float v = w1[(size_t)k * HH + nx + tx] * 32.0f;
        float h = __half2float(__float2half_rn(v));
        th[ty + j * 8][tx] = h;
        tl[ty + j * 8][tx] = v - h;
    }
    __syncthreads();
    #pragma unroll
    for (int j = 0; j < 4; j++) {
        int n = nx + ty + j * 8;
        d_w1ht[(size_t)n * DD + ky + tx] = __float2half_rn(th[tx][ty + j * 8]);
        d_w1lt[(size_t)n * DD + ky + tx] = __float2half_rn(tl[tx][ty + j * 8]);
    }
}

// ---------------- 2) LayerNorm (compacted) + fp16 hi/lo split (x32) ----------
__global__ __launch_bounds__(192) void k_ln(const float* __restrict__ emb,
                                            const float* __restrict__ g,
                                            const float* __restrict__ bb) {
    int r = blockIdx.x;
    if (r >= d_nv) return;
    int tok = d_validx[r];
    const float4* x4 = (const float4*)(emb + (size_t)tok * DD);
    int t = threadIdx.x;
    float4 v = x4[t];
    __shared__ float red[192];

    red[t] = v.x + v.y + v.z + v.w; __syncthreads();
    if (t < 64) red[t] += red[t + 64] + red[t + 128];
    __syncthreads();
    #pragma unroll
    for (int o = 32; o > 0; o >>= 1) { if (t < o) red[t] += red[t + o]; __syncthreads(); }
    float mu = red[0] * (1.0f / (float)DD);
    __syncthreads();

    float ex = v.x - mu, ey = v.y - mu, ez = v.z - mu, ew = v.w - mu;
    red[t] = ex * ex + ey * ey + ez * ez + ew * ew; __syncthreads();
    if (t < 64) red[t] += red[t + 64] + red[t + 128];
    __syncthreads();
    #pragma unroll
    for (int o = 32; o > 0; o >>= 1) { if (t < o) red[t] += red[t + o]; __syncthreads(); }
    float inv = rsqrtf(red[0] * (1.0f / (float)DD) + 1e-5f);

    float4 gv = ((const float4*)g)[t];
    float4 bv = ((const float4*)bb)[t];
    float o0 = (ex * inv * gv.x + bv.x) * 32.0f;
    float o1 = (ey * inv * gv.y + bv.y) * 32.0f;
    float o2 = (ez * inv * gv.z + bv.z) * 32.0f;
    float o3 = (ew * inv * gv.w + bv.w) * 32.0f;
    __half h0 = __float2half_rn(o0), h1 = __float2half_rn(o1);
    __half h2 = __float2half_rn(o2), h3 = __float2half_rn(o3);
    __half l0 = __float2half_rn(o0 - __half2float(h0));
    __half l1 = __float2half_rn(o1 - __half2float(h1));
    __half l2 = __float2half_rn(o2 - __half2float(h2));
    __half l3 = __float2half_rn(o3 - __half2float(h3));
    __half2* ph = (__half2*)(d_xh + (size_t)r * DD);
    __half2* pl = (__half2*)(d_xl + (size_t)r * DD);
    ph[2 * t]     = __halves2half2(h0, h1);
    ph[2 * t + 1] = __halves2half2(h2, h3);
    pl[2 * t]     = __halves2half2(l0, l1);
    pl[2 * t + 1] = __halves2half2(l2, l3);
}

// ---------------- 3) GEMM: fp16 2-split m16n8k16 + ldmatrix + cp.async -------
// R14-validated config (312 us): CTA 128x128, 256 thr, k16 stages, occ 2.
#define MATB 20480
#define STGB 10240
#define RB_B  81920         // rbuf 128x2 floats
#define B1_B  82944         // 128 floats
#define W2_B  83456         // 128 floats
#define GEMM_SMEM_BYTES 83968
#define NKT (DD / 16)       // 48 k-tiles

__global__ __launch_bounds__(256, 2) void k_gemm(const float* __restrict__ b1,
                                                 const float* __restrict__ w2) {
    extern __shared__ char smc[];
    int nv = d_nv;
    int n0 = blockIdx.x * 128;
    int row0 = blockIdx.y * 128;
    if (row0 >= nv) return;

    int tid = threadIdx.x;
    int lane = tid & 31, wid = tid >> 5;
    int warp_m = wid >> 1, warp_n = wid & 1;
    int lq = lane >> 2, lp = lane & 3;

    float* b1s = (float*)(smc + B1_B);
    float* w2s = (float*)(smc + W2_B);
    if (tid < 128) { b1s[tid] = b1[n0 + tid]; w2s[tid] = w2[n0 + tid]; }

    // loader: mat = tid>>6 (0=Ah 1=Al 2=Bh 3=Bl), 64 thr/mat, 2 rows x 2 chunks
    int mat = tid >> 6;
    int t2 = tid & 63;
    uint32_t smem_base = s2u32(smc);
    const __half* gsrc;
    int gb;
    if      (mat == 0) { gsrc = d_xh;   gb = row0; }
    else if (mat == 1) { gsrc = d_xl;   gb = row0; }
    else if (mat == 2) { gsrc = d_w1ht; gb = n0; }
    else               { gsrc = d_w1lt; gb = n0; }
    int r0 = t2 * 2;
    uint32_t sMat = smem_base + mat * MATB;

    float acc[2][8][4];
    #pragma unroll
    for (int mt = 0; mt < 2; mt++)
        #pragma unroll
        for (int nt = 0; nt < 8; nt++)
            #pragma unroll
            for (int q = 0; q < 4; q++) acc[mt][nt][q] = 0.f;

    #define PREFETCH(ii, ss) do {                                              \
        const __half* _g0 = gsrc + (size_t)(gb + r0) * DD + (ii) * 16;         \
        const __half* _g1 = _g0 + DD;                                          \
        uint32_t _s = sMat + (ss) * STGB + r0 * 80;                            \
        cp16(_s,           _g0);                                               \
        cp16(_s + 16,      _g0 + 8);                                           \
        cp16(_s + 80,      _g1);                                               \
        cp16(_s + 96,      _g1 + 8);                                           \
    } while (0)

    PREFETCH(0, 0);
    CP_COMMIT();

    uint32_t aH = smem_base;
    uint32_t aL = smem_base + MATB;
    uint32_t bH = smem_base + 2 * MATB;
    uint32_t bL = smem_base + 3 * MATB;
    int Rm = warp_m * 32;
    int Nn = warp_n * 64;

    uint32_t aOff = (uint32_t)((Rm + (lane & 15)) * 80 + (lane >> 4) * 16);
    uint32_t bOff = (uint32_t)((Nn + ((lane >> 4) << 3) + (lane & 7)) * 80
                               + ((lane >> 3) & 1) * 16);

    for (int i = 0; i < NKT; i++) {
        int s = i & 1;
        if (i + 1 < NKT) {
            PREFETCH(i + 1, s ^ 1);
            CP_COMMIT();
            CP_WAIT(1);
        } else {
            CP_WAIT(0);
        }
        __syncthreads();

        uint32_t stg = s * STGB;
        unsigned ah[2][4], al[2][4];
        #pragma unroll
        for (int mt = 0; mt < 2; mt++) {
            ldsm4(ah[mt], aH + stg + aOff + mt * 1280);
            ldsm4(al[mt], aL + stg + aOff + mt * 1280);
        }
        #pragma unroll
        for (int p = 0; p < 4; p++) {       // nt-pairs (2p, 2p+1)
            unsigned bhf[4], blf[4];
            ldsm4(bhf, bH + stg + bOff + p * 1280);
            ldsm4(blf, bL + stg + bOff + p * 1280);
            #pragma unroll
            for (int h = 0; h < 2; h++) {
                int nt = 2 * p + h;
                unsigned b0h = bhf[h * 2], b1h = bhf[h * 2 + 1];
                unsigned b0l = blf[h * 2], b1l = blf[h * 2 + 1];
                #pragma unroll
                for (int mt = 0; mt < 2; mt++) {
                    mma_f16(acc[mt][nt], ah[mt], b0h, b1h);  // hi*hi
                    mma_f16(acc[mt][nt], ah[mt], b0l, b1l);  // hi*lo
                    mma_f16(acc[mt][nt], al[mt], b0h, b1h);  // lo*hi
                }
            }
        }
        __syncthreads();
    }

    // epilogue: unscale (1/1024) + bias + exact GELU + w2, warp-reduce 64 cols
    float* rbuf = (float*)(smc + RB_B);
    #pragma unroll
    for (int mt = 0; mt < 2; mt++) {
        #pragma unroll
        for (int half = 0; half < 2; half++) {
            float p = 0.f;
            #pragma unroll
            for (int nt = 0; nt < 8; nt++) {
                int col = warp_n * 64 + nt * 8 + 2 * lp;
                float v0 = acc[mt][nt][half * 2]     * (1.0f / 1024.0f);
                float v1 = acc[mt][nt][half * 2 + 1] * (1.0f / 1024.0f);
                float h0 = v0 + b1s[col];
                float h1 = v1 + b1s[col + 1];
                float g0 = 0.5f * h0 * (1.0f + erff(h0 * 0.70710678118654752440f));
                float g1 = 0.5f * h1 * (1.0f + erff(h1 * 0.70710678118654752440f));
                p += g0 * w2s[col] + g1 * w2s[col + 1];
            }
            p += __shfl_xor_sync(0xffffffffu, p, 1);
            p += __shfl_xor_sync(0xffffffffu, p, 2);
            if (lp == 0)
                rbuf[(warp_m * 32 + mt * 16 + half * 8 + lq) * 2 + warp_n] = p;
        }
    }
    __syncthreads();
    if (tid < 128) {
        int row = row0 + tid;
        if (row < nv)
            d_part[blockIdx.x][row] = rbuf[tid * 2] + rbuf[tid * 2 + 1];
    }
}

// ---------------- 4a) per-batch score normalization ----------------
__global__ __launch_bounds__(1024) void k_score(const int* __restrict__ attn,
                                                const float* __restrict__ b2) {
    int b = blockIdx.x, j = threadIdx.x;
    __shared__ float red[1024];
    int idx = b * TT + j;
    float a = (attn[idx] != 0) ? 1.f : 0.f;
    float sraw = 0.f;
    if (a > 0.f) {
        int row = d_rowof[idx];
        float s = 0.f;
        #pragma unroll
        for (int n = 0; n < 8; n++) s += d_part[n][row];
        sraw = s + b2[0];
    }
    float denom = fmaxf(d_Teff[b], 1.0f);
    float S1 = bsum1024(sraw, red);
    float mean = S1 / denom;
    float dv = sraw - mean;
    float S2 = bsum1024(dv * dv * a, red);
    float var = S2 / denom;
    d_snorm[idx] = (sraw - mean) / sqrtf(var + 1e-6f);
}

// ---------------- 4b) pairwise soft-rank (chip-wide, MUFU path) --------------
__global__ __launch_bounds__(256) void k_pair(const int* __restrict__ attn) {
    int b = blockIdx.x;
    __shared__ float sn[1024];
    for (int i = threadIdx.x; i < 1024; i += 256)
        sn[i] = d_snorm[b * TT + i] * 20.0f;      // pre-scale by 1/tau
    __syncthreads();
    int j = blockIdx.y * 256 + threadIdx.x;
    int idx = b * TT + j;
    if (attn[idx] == 0) { d_rankv[idx] = 1e9f; return; }
    float sj = sn[j];
    float a0 = 0.f, a1 = 0.f, a2 = 0.f, a3 = 0.f;
    #pragma unroll 2
    for (int i = 0; i < 1024; i += 4) {
        float e0 = __expf(sn[i]     - sj); float s0 = __fdividef(1.f, 1.f + e0); a0 += s0 * s0;
        float e1 = __expf(sn[i + 1] - sj); float s1 = __fdividef(1.f, 1.f + e1); a1 += s1 * s1;
        float e2 = __expf(sn[i + 2] - sj); float s2 = __fdividef(1.f, 1.f + e2); a2 += s2 * s2;
        float e3 = __expf(sn[i + 3] - sj); float s3 = __fdividef(1.f, 1.f + e3); a3 += s3 * s3;
    }
    d_rankv[idx] = 1.f + ((a0 + a1) + (a2 + a3));
}

// ---------------- 4c) ascending-rank position (chip-wide) ----------------
__global__ __launch_bounds__(256) void k_pos() {
    int b = blockIdx.x;
    __shared__ float rk[1024];
    for (int i = threadIdx.x; i < 1024; i += 256) rk[i] = d_rankv[b * TT + i];
    __syncthreads();
    int j = blockIdx.y * 256 + threadIdx.x;
    float r = rk[j];
    int pos = 0;
    #pragma unroll 4
    for (int i = 0; i < 1024; i++) {
        float ri = rk[i];
        pos += (ri < r) || (ri == r && i < j);
    }
    d_pos[b * TT + j] = pos;
}

// ---------------- 4d) gates + hard masks + per-batch sums ----------------
__global__ __launch_bounds__(1024) void k_gate(const int* __restrict__ attn,
                                               float* __restrict__ out) {
    int b = blockIdx.x, j = threadIdx.x;
    __shared__ float red[1024];
    int idx = b * TT + j;
    float a = (attn[idx] != 0) ? 1.f : 0.f;
    float r = d_rankv[idx];
    float fpos = (float)d_pos[idx];
    float Teff = d_Teff[b];

    const float rhos[3] = {0.1f, 0.25f, 0.5f};
    #pragma unroll
    for (int q = 0; q < 3; q++) {
        float k = fmaxf(rintf(rhos[q] * Teff), 1.0f);
        float gate = (a > 0.f) ? 1.f / (1.f + __expf(-(k - r) * 5.0f)) : 0.f;
        float Sg = bsum1024(gate, red);
        float g = gate / fmaxf(Sg, 1e-8f) * k;
        d_gall[q][idx] = g;
        if (q == 2) out[idx] = g;
        out[OFF_HARD + q * BT + idx] = (fpos < k) ? 1.f : 0.f;
        float Sg2 = bsum1024(g, red);
        if (j == 0) {
            d_keff[q][b] = Sg2;
            out[OFF_RHOE + q * BB + b] = Sg2 / fmaxf(Teff, 1.0f);
        }
    }
}

// ---------------- 5) pooled representations (4 weightings, one pass) ---------
__global__ __launch_bounds__(256) void k_pool(const int* __restrict__ ids,
                                              const int* __restrict__ attn,
                                              const float* __restrict__ etab) {
    int b = blockIdx.x;
    int t0 = blockIdx.y * 64;
    int tid = threadIdx.x;
    float accF[3] = {0, 0, 0}, ac0[3] = {0, 0, 0}, ac1[3] = {0, 0, 0}, ac2[3] = {0, 0, 0};
    for (int t = t0; t < t0 + 64; t++) {
        int idx = b * TT + t;
        if (attn[idx] == 0) continue;
        int id = ids[idx];
        float w0 = d_gall[0][idx], w1v = d_gall[1][idx], w2v = d_gall[2][idx];
        const float* row = etab + (size_t)id * DD;
        #pragma unroll
        for (int i = 0; i < 3; i++) {
            float v = __ldg(row + tid + 256 * i);
            accF[i] += v; ac0[i] += v * w0; ac1[i] += v * w1v; ac2[i] += v * w2v;
        }
    }
    #pragma unroll
    for (int i = 0; i < 3; i++) {
        int d = tid + 256 * i;
        atomicAdd(&d_poolacc[0][b][d], accF[i]);
        atomicAdd(&d_poolacc[1][b][d], ac0[i]);
        atomicAdd(&d_poolacc[2][b][d], ac1[i]);
        atomicAdd(&d_poolacc[3][b][d], ac2[i]);
    }
}

// ---------------- 6) losses ----------------
__global__ __launch_bounds__(1024) void k_final(float* __restrict__ out) {
    int t = threadIdx.x;
    __shared__ float red[1024];
    __shared__ float sl[3];
    for (int q = 0; q < 3; q++) {
        float s = 0.f;
        for (int n = t; n < BB * DD; n += 1024) {
            int b = n / DD, d = n % DD;
            float Te = d_Teff[b];
            float full = d_poolacc[0][b][d] / fmaxf(Te, 1e-9f);
            float pred = d_poolacc[1 + q][b][d] / fmaxf(d_keff[q][b], 1e-9f);
            float df = pred - full;
            s += df * df;
        }
        float S = bsum1024(s, red);
        if (t == 0) sl[q] = S / (float)(BB * DD);
        __syncthreads();
    }
    if (t == 0) {
        float l0 = sl[0], l1 = sl[1], l2 = sl[2];
        out[OFF_RECON] = ((l0 + l1) + l2) / 3.0f;
        out[OFF_LOSS + 0] = l0;
        out[OFF_LOSS + 1] = l1;
        out[OFF_LOSS + 2] = l2;
    }
}

// ---------------- launch ----------------
extern "C" void kernel_launch(void* const* d_in, const int* in_sizes, int n_in,
                              void* d_out, int out_size) {
    const int*   ids  = (const int*)d_in[0];
    const float* emb  = (const float*)d_in[1];
    const int*   attn = (const int*)d_in[2];
    const float* ln_g = (const float*)d_in[3];
    const float* ln_b = (const float*)d_in[4];
    const float* w1   = (const float*)d_in[5];
    const float* b1   = (const float*)d_in[6];
    const float* w2   = (const float*)d_in[7];
    const float* b2   = (const float*)d_in[8];
    const float* etab = (const float*)d_in[9];
    float* out = (float*)d_out;

    static int smem_set = 0;
    if (!smem_set) {
        cudaFuncSetAttribute(k_gemm, cudaFuncAttributeMaxDynamicSharedMemorySize,
                             GEMM_SMEM_BYTES);
        smem_set = 1;
    }

    k_compact<<<1, 1024>>>(attn);
    dim3 gw(HH / 32, DD / 32);
    k_splitw_t<<<gw, 256>>>(w1);
    k_ln<<<BT, 192>>>(emb, ln_g, ln_b);
    dim3 gg(HH / 128, BT / 128);           // x = col tile fastest -> A reuse in L2
    k_gemm<<<gg, 256, GEMM_SMEM_BYTES>>>(b1, w2);
    k_score<<<BB, 1024>>>(attn, b2);
    dim3 gr(BB, TT / 256);
    k_pair<<<gr, 256>>>(attn);
    k_pos<<<gr, 256>>>();
    k_gate<<<BB, 1024>>>(attn, out);
    dim3 gp(BB, TT / 64);
    k_pool<<<gp, 256>>>(ids, attn, etab);
    k_final<<<1, 1024>>>(out);
}